// round 4
// baseline (speedup 1.0000x reference)
#include <cuda_runtime.h>
#include <cstdint>

// ============================================================================
// SequenceMemoryUpdater v4 — mma.sync tf32 + bulk-copy staging + overlapped copy
//
//   main stream: zero_mask -> set_mask -> lu_copy -> [fork] -> gru -> [join]
//   side stream:                         [fork] -> masked copy_mem -> [join]
//
// GRU kernel (per 64-row tile):
//   gates[b,0:512]: 0..127 r, 128..255 z, 256..383 i_n (x-K), 384..511 h_n (h-K)
//   12 K-chunks of 32. Chunk staging = 448 x 128B cp.async.bulk (warp 0 only)
//   into a 3-slot ring, completion via mbarrier expect_tx. mma.sync tf32 with
//   raw-fp32 operands (HW truncation). Register-resident GRU epilogue.
// ============================================================================

#define BLOCK_M   64
#define THREADS   512

// smem byte offsets
#define OFF_MBAR   0            // 3 mbarriers (8B each)
#define OFF_BIAS   64           // 512 floats
#define OFF_IDS    2112         // 64 ints
#define OFF_SLOT0  2432         // 3 slots x 64512B; slot: W 384x36f, A 64x36f
#define SLOT_BYTES 64512
#define SLOT_A_OFF 55296        // A tile starts after 384*144B of W
#define SMEM_BYTES (OFF_SLOT0 + 3 * SLOT_BYTES)   // 195968

#define MASK_WORDS 32768        // 1M nodes / 32
__device__ uint32_t g_mask[MASK_WORDS];

// ---- PTX helpers (all sm_90-base legal) ----
#define MBAR_INIT(addr, cnt) \
    asm volatile("mbarrier.init.shared.b64 [%0], %1;" :: "r"(addr), "r"(cnt) : "memory")
#define MBAR_EXPECT_TX(addr, bytes) \
    asm volatile("mbarrier.arrive.expect_tx.shared.b64 _, [%0], %1;" \
                 :: "r"(addr), "r"(bytes) : "memory")
#define FENCE_ASYNC() asm volatile("fence.proxy.async.shared::cta;" ::: "memory")

__device__ __forceinline__ void mbar_wait(uint32_t addr, uint32_t parity) {
    asm volatile(
        "{\n\t.reg .pred P;\n"
        "W_%=:\n\t"
        "mbarrier.try_wait.parity.acquire.cta.shared::cta.b64 P, [%0], %1, 0x989680;\n\t"
        "@P bra.uni D_%=;\n\t"
        "bra.uni W_%=;\n"
        "D_%=:\n\t}"
        :: "r"(addr), "r"(parity) : "memory");
}

__device__ __forceinline__ void bulk_cp128(uint32_t dst_smem, const void* src,
                                           uint32_t mbar) {
    asm volatile(
        "cp.async.bulk.shared::cluster.global.mbarrier::complete_tx::bytes "
        "[%0], [%1], 128, [%2];"
        :: "r"(dst_smem), "l"(src), "r"(mbar) : "memory");
}

// raw fp32 bits fed as tf32 (HW truncates low 13 mantissa bits)
__device__ __forceinline__ void mma_tf32(float* d, const float* a,
                                         float b0, float b1) {
    asm volatile(
        "mma.sync.aligned.m16n8k8.row.col.f32.tf32.tf32.f32 "
        "{%0,%1,%2,%3}, {%4,%5,%6,%7}, {%8,%9}, {%0,%1,%2,%3};"
        : "+f"(d[0]), "+f"(d[1]), "+f"(d[2]), "+f"(d[3])
        : "r"(__float_as_uint(a[0])), "r"(__float_as_uint(a[1])),
          "r"(__float_as_uint(a[2])), "r"(__float_as_uint(a[3])),
          "r"(__float_as_uint(b0)),  "r"(__float_as_uint(b1)));
}

__device__ __forceinline__ float gru_one(float pr, float pz, float pin,
                                         float phn, float h) {
    float r = 1.0f / (1.0f + __expf(-pr));
    float z = 1.0f / (1.0f + __expf(-pz));
    float n = tanhf(fmaf(r, phn, pin));
    return fmaf(z, h - n, n);   // (1-z)*n + z*h
}

// ---------------------------------------------------------------------------
// mask kernels
// ---------------------------------------------------------------------------
__global__ void zero_mask_kernel(int n_words) {
    int i = blockIdx.x * blockDim.x + threadIdx.x;
    if (i < n_words) g_mask[i] = 0u;
}
__global__ void set_mask_kernel(const int* __restrict__ ids, int B) {
    int i = blockIdx.x * blockDim.x + threadIdx.x;
    if (i < B) {
        int node = ids[i];
        atomicOr(&g_mask[node >> 5], 1u << (node & 31));
    }
}

// ---------------------------------------------------------------------------
// copies
// ---------------------------------------------------------------------------
__global__ void lu_copy_kernel(const float4* __restrict__ lu,
                               float4* __restrict__ out, int n4) {
    int i = blockIdx.x * blockDim.x + threadIdx.x;
    if (i < n4) out[i] = lu[i];
}

// one warp == one 128-float row; skip rows GRU will write
__global__ void copy_mem_kernel(const float4* __restrict__ mem,
                                float4* __restrict__ out, int n_rows) {
    int idx = blockIdx.x * blockDim.x + threadIdx.x;   // float4 index
    int row = idx >> 5;
    if (row >= n_rows) return;
    if ((g_mask[row >> 5] >> (row & 31)) & 1u) return;
    out[idx] = mem[idx];
}

// ---------------------------------------------------------------------------
// stage chunk kc into ring slot kc%3 via cp.async.bulk (called by warp 0 only)
// 448 rows of 128B: rows 0..383 = W chunk, rows 384..447 = A chunk
// ---------------------------------------------------------------------------
__device__ __forceinline__ void stage_bulk(uint32_t smb, int kc,
                                           const float* __restrict__ messages,
                                           const float* __restrict__ memory,
                                           const int* __restrict__ ids_s,
                                           const float* __restrict__ W_ih,
                                           const float* __restrict__ W_hh,
                                           int row0, int B, int lane) {
    const int slot = kc % 3;
    const uint32_t mbar = smb + OFF_MBAR + 8 * slot;
    const uint32_t base = smb + OFF_SLOT0 + slot * SLOT_BYTES;
    if (lane == 0) MBAR_EXPECT_TX(mbar, 448u * 128u);
    __syncwarp();
    const float* W = (kc < 8) ? W_ih : W_hh;
    const size_t stride = (kc < 8) ? 256 : 128;
    const int col0 = ((kc < 8) ? kc : kc - 8) * 32;
#pragma unroll
    for (int i = 0; i < 14; ++i) {
        int r = i * 32 + lane;
        if (r < 384) {
            bulk_cp128(base + r * 144, W + (size_t)r * stride + col0, mbar);
        } else {
            int j = r - 384;
            const float* src;
            if (kc < 8) {
                int gr = row0 + j; if (gr >= B) gr = B - 1;
                src = messages + (size_t)gr * 256 + col0;
            } else {
                src = memory + (size_t)ids_s[j] * 128 + col0;
            }
            bulk_cp128(base + SLOT_A_OFF + j * 144, src, mbar);
        }
    }
}

// ---------------------------------------------------------------------------
// per-chunk MMA body; G2 = accumulator slot for the third gate (2=i_n, 3=h_n)
// A tile: 64 rows x 32 (stride 36 floats), W tile: 384 x 32 (stride 36)
// ---------------------------------------------------------------------------
template<int G2>
__device__ __forceinline__ void mma_chunk(float (&acc)[2][4][2][4],
                                          const float* A, const float* Ws,
                                          int wm, int wq, int lane) {
    const float* arow = A + (wm * 32 + (lane >> 2)) * 36 + (lane & 3);
    const float* bbas = Ws + (wq * 16 + (lane >> 2)) * 36 + (lane & 3);
#pragma unroll
    for (int k8 = 0; k8 < 4; ++k8) {
        float a[2][4];
#pragma unroll
        for (int mt = 0; mt < 2; ++mt) {
            const float* ap = arow + mt * 16 * 36 + k8 * 8;
            a[mt][0] = ap[0];
            a[mt][1] = ap[8 * 36];
            a[mt][2] = ap[4];
            a[mt][3] = ap[8 * 36 + 4];
        }
#pragma unroll
        for (int gate = 0; gate < 3; ++gate) {
            const int gi = (gate == 2) ? G2 : gate;
#pragma unroll
            for (int sub = 0; sub < 2; ++sub) {
                const float* bp = bbas + (gate * 128 + sub * 8) * 36 + k8 * 8;
                float b0 = bp[0], b1 = bp[4];
                mma_tf32(acc[0][gi][sub], a[0], b0, b1);
                mma_tf32(acc[1][gi][sub], a[1], b0, b1);
            }
        }
    }
}

// ---------------------------------------------------------------------------
// GRU kernel
// ---------------------------------------------------------------------------
__global__ void __launch_bounds__(THREADS, 1)
gru_update_kernel(const float* __restrict__ memory,
                  const int*   __restrict__ ids,
                  const float* __restrict__ messages,
                  const float* __restrict__ ts,
                  const float* __restrict__ W_ih,
                  const float* __restrict__ W_hh,
                  const float* __restrict__ b_ih,
                  const float* __restrict__ b_hh,
                  float* __restrict__ out_mem,
                  float* __restrict__ out_lu,
                  int B) {
    extern __shared__ char sm[];
    const uint32_t smb = (uint32_t)__cvta_generic_to_shared(sm);
    float* smf = (float*)sm;
    const int tid  = threadIdx.x;
    const int lane = tid & 31;
    const int warp = tid >> 5;
    const int row0 = blockIdx.x * BLOCK_M;
    const int wm = warp & 1;       // 32-row half
    const int wq = warp >> 1;      // 16-h-col group

    int* ids_s  = (int*)(sm + OFF_IDS);
    float* bias = (float*)(sm + OFF_BIAS);

    // ---- phase 0: ids, fused biases, mbarriers ----
    if (tid < BLOCK_M) {
        int gr = row0 + tid;
        ids_s[tid] = (gr < B) ? ids[gr] : 0;
    }
    {
        float v;
        if (tid < 256)      v = b_ih[tid] + b_hh[tid];      // r,z
        else if (tid < 384) v = b_ih[tid];                  // i_n
        else                v = b_hh[tid - 128];            // h_n
        bias[tid] = v;
    }
    if (tid == 0) {
        MBAR_INIT(smb + OFF_MBAR + 0, 1);
        MBAR_INIT(smb + OFF_MBAR + 8, 1);
        MBAR_INIT(smb + OFF_MBAR + 16, 1);
    }
    FENCE_ASYNC();
    __syncthreads();

    // ---- prolog: warp 0 stages chunks 0,1,2 ----
    if (warp == 0) {
        stage_bulk(smb, 0, messages, memory, ids_s, W_ih, W_hh, row0, B, lane);
        stage_bulk(smb, 1, messages, memory, ids_s, W_ih, W_hh, row0, B, lane);
        stage_bulk(smb, 2, messages, memory, ids_s, W_ih, W_hh, row0, B, lane);
    }

    float acc[2][4][2][4];                 // [mt][gate r/z/in/hn][sub][c]
#pragma unroll
    for (int mt = 0; mt < 2; ++mt)
#pragma unroll
        for (int g = 0; g < 4; ++g)
#pragma unroll
            for (int s = 0; s < 2; ++s)
#pragma unroll
                for (int c = 0; c < 4; ++c) acc[mt][g][s][c] = 0.0f;

    // ---- main loop: 12 K-chunks (0..7 = x / i_n, 8..11 = h / h_n) ----
    for (int kc = 0; kc < 12; ++kc) {
        const int slot = kc % 3;
        mbar_wait(smb + OFF_MBAR + 8 * slot, (kc / 3) & 1);
        const float* W = smf + (OFF_SLOT0 + slot * SLOT_BYTES) / 4;
        const float* A = W + SLOT_A_OFF / 4;
        if (kc < 8) mma_chunk<2>(acc, A, W, wm, wq, lane);
        else        mma_chunk<3>(acc, A, W, wm, wq, lane);
        __syncthreads();                  // all reads of this slot done
        if (warp == 0 && kc + 3 < 12)
            stage_bulk(smb, kc + 3, messages, memory, ids_s, W_ih, W_hh,
                       row0, B, lane);
    }

    // ---- register-resident GRU epilogue + scatter (h re-read from gmem) ----
#pragma unroll
    for (int mt = 0; mt < 2; ++mt) {
#pragma unroll
        for (int half = 0; half < 2; ++half) {     // acc c{0,1} vs c{2,3}
            int row_l = wm * 32 + mt * 16 + (lane >> 2) + half * 8;
            int gr = row0 + row_l;
            int node = ids_s[row_l];
            const float* hrow = memory + (size_t)node * 128;
            float* orow = out_mem + (size_t)node * 128;
            const int c0 = half * 2;
#pragma unroll
            for (int sub = 0; sub < 2; ++sub) {
                int hc = wq * 16 + sub * 8 + (lane & 3) * 2;
                float2 ho = *(const float2*)(hrow + hc);
                float2 br = *(const float2*)(bias + hc);
                float2 bz = *(const float2*)(bias + 128 + hc);
                float2 bi = *(const float2*)(bias + 256 + hc);
                float2 bh = *(const float2*)(bias + 384 + hc);
                float2 res;
                res.x = gru_one(acc[mt][0][sub][c0]     + br.x,
                                acc[mt][1][sub][c0]     + bz.x,
                                acc[mt][2][sub][c0]     + bi.x,
                                acc[mt][3][sub][c0]     + bh.x, ho.x);
                res.y = gru_one(acc[mt][0][sub][c0 + 1] + br.y,
                                acc[mt][1][sub][c0 + 1] + bz.y,
                                acc[mt][2][sub][c0 + 1] + bi.y,
                                acc[mt][3][sub][c0 + 1] + bh.y, ho.y);
                if (gr < B) *(float2*)(orow + hc) = res;
            }
        }
    }
    if (tid < BLOCK_M) {
        int gr = row0 + tid;
        if (gr < B) out_lu[ids_s[tid]] = ts[gr];
    }
}

// ---------------------------------------------------------------------------
extern "C" void kernel_launch(void* const* d_in, const int* in_sizes, int n_in,
                              void* d_out, int out_size) {
    const float* memory      = (const float*)d_in[0];
    const float* last_update = (const float*)d_in[1];
    const int*   ids         = (const int*)d_in[2];
    const float* messages    = (const float*)d_in[3];
    const float* ts          = (const float*)d_in[4];
    const float* W_ih        = (const float*)d_in[5];
    const float* W_hh        = (const float*)d_in[6];
    const float* b_ih        = (const float*)d_in[7];
    const float* b_hh        = (const float*)d_in[8];

    const int n_nodes = in_sizes[1];
    const int B       = in_sizes[2];

    float* out_mem = (float*)d_out;
    float* out_lu  = out_mem + (size_t)n_nodes * 128;

    // one-time setup on the (uncaptured) correctness call
    static bool inited = false;
    static cudaStream_t s_side;
    static cudaEvent_t e_fork, e_join;
    if (!inited) {
        cudaStreamCreateWithFlags(&s_side, cudaStreamNonBlocking);
        cudaEventCreateWithFlags(&e_fork, cudaEventDisableTiming);
        cudaEventCreateWithFlags(&e_join, cudaEventDisableTiming);
        cudaFuncSetAttribute(gru_update_kernel,
                             cudaFuncAttributeMaxDynamicSharedMemorySize,
                             SMEM_BYTES);
        inited = true;
    }

    // main stream: mask build + lu copy
    zero_mask_kernel<<<(MASK_WORDS + 255) / 256, 256>>>(MASK_WORDS);
    set_mask_kernel<<<(B + 255) / 256, 256>>>(ids, B);
    lu_copy_kernel<<<(n_nodes / 4 + 255) / 256, 256>>>(
        (const float4*)last_update, (float4*)out_lu, n_nodes / 4);

    // fork: masked bulk copy of memory on side stream, GRU on main stream
    cudaEventRecord(e_fork, 0);
    cudaStreamWaitEvent(s_side, e_fork, 0);
    {
        long long n4 = (long long)n_nodes * 32;
        copy_mem_kernel<<<(unsigned)((n4 + 255) / 256), 256, 0, s_side>>>(
            (const float4*)memory, (float4*)out_mem, n_nodes);
    }
    cudaEventRecord(e_join, s_side);

    int tiles = (B + BLOCK_M - 1) / BLOCK_M;
    gru_update_kernel<<<tiles, THREADS, SMEM_BYTES>>>(
        memory, ids, messages, ts, W_ih, W_hh, b_ih, b_hh,
        out_mem, out_lu, B);

    // join
    cudaStreamWaitEvent(0, e_join, 0);
}